// round 5
// baseline (speedup 1.0000x reference)
#include <cuda_runtime.h>
#include <math.h>

// Problem constants
#define TT 512     // timesteps
#define BB 64      // batch
#define II 512     // input dim
#define HH 1024    // hidden dim
#define G4 4096    // 4*H gate dim
#define NSTEP 1024 // TT * NUM_LAYERS
#define NBLK 128   // persistent blocks (<= SM count, all co-resident)

// Scratch: precomputed input projection Xg[t][b][4H] = x@Ww.T + bw + bu  (512 MB)
__device__ float g_xg[(size_t)TT * BB * G4];

// Grid barrier state (sense-reversing; returns to {0,0} after every launch
// because 1024 barriers = even number of sense flips)
__device__ int g_count;
__device__ int g_sense;

// ---------------------------------------------------------------------------
// Kernel 1: Xg = x @ Ww.T + (bw + bu)
// M = TT*BB = 32768 rows (row r -> t = r/64, b = r%64), N = 4096, K = 512.
// 128x128 tile, BK=16, 256 threads, 8x8 microtile.
// ---------------------------------------------------------------------------
#define XG_BM 128
#define XG_BN 128
#define XG_BK 16

__global__ __launch_bounds__(256) void xg_kernel(
    const float* __restrict__ x,   // [B, T, I]
    const float* __restrict__ Ww,  // [4H, I]
    const float* __restrict__ bw,  // [4H]
    const float* __restrict__ bu)  // [4H]
{
    __shared__ float As[XG_BK][XG_BM + 4];
    __shared__ float Bs[XG_BK][XG_BN + 4];

    const int tid = threadIdx.x;
    const int m0 = blockIdx.y * XG_BM;
    const int n0 = blockIdx.x * XG_BN;
    const int ty = tid >> 4;   // 0..15
    const int tx = tid & 15;   // 0..15

    float acc[8][8];
#pragma unroll
    for (int i = 0; i < 8; i++)
#pragma unroll
        for (int j = 0; j < 8; j++) acc[i][j] = 0.f;

    for (int k0 = 0; k0 < II; k0 += XG_BK) {
#pragma unroll
        for (int l = 0; l < 2; l++) {
            int fq = l * 256 + tid;       // 0..511
            int r  = fq >> 2;             // 0..127
            int kq = (fq & 3) * 4;        // 0,4,8,12
            int gr = m0 + r;
            int b  = gr & 63;
            int t  = gr >> 6;
            const float4 v = *(const float4*)(x + ((size_t)(b * TT + t)) * II + k0 + kq);
            As[kq + 0][r] = v.x;
            As[kq + 1][r] = v.y;
            As[kq + 2][r] = v.z;
            As[kq + 3][r] = v.w;
        }
#pragma unroll
        for (int l = 0; l < 2; l++) {
            int fq = l * 256 + tid;
            int n  = fq >> 2;
            int kq = (fq & 3) * 4;
            const float4 v = *(const float4*)(Ww + (size_t)(n0 + n) * II + k0 + kq);
            Bs[kq + 0][n] = v.x;
            Bs[kq + 1][n] = v.y;
            Bs[kq + 2][n] = v.z;
            Bs[kq + 3][n] = v.w;
        }
        __syncthreads();

#pragma unroll
        for (int kk = 0; kk < XG_BK; kk++) {
            float a[8], bb[8];
#pragma unroll
            for (int i = 0; i < 8; i++) a[i] = As[kk][ty * 8 + i];
#pragma unroll
            for (int j = 0; j < 8; j++) bb[j] = Bs[kk][tx * 8 + j];
#pragma unroll
            for (int i = 0; i < 8; i++)
#pragma unroll
                for (int j = 0; j < 8; j++) acc[i][j] += a[i] * bb[j];
        }
        __syncthreads();
    }

    float bsum[8];
#pragma unroll
    for (int j = 0; j < 8; j++) {
        int gn = n0 + tx * 8 + j;
        bsum[j] = bw[gn] + bu[gn];
    }
#pragma unroll
    for (int i = 0; i < 8; i++) {
        int gm = m0 + ty * 8 + i;
        float* row = g_xg + (size_t)gm * G4 + n0 + tx * 8;
        float4 v0, v1;
        v0.x = acc[i][0] + bsum[0];
        v0.y = acc[i][1] + bsum[1];
        v0.z = acc[i][2] + bsum[2];
        v0.w = acc[i][3] + bsum[3];
        v1.x = acc[i][4] + bsum[4];
        v1.y = acc[i][5] + bsum[5];
        v1.z = acc[i][6] + bsum[6];
        v1.w = acc[i][7] + bsum[7];
        *(float4*)(row)     = v0;
        *(float4*)(row + 4) = v1;
    }
}

// ---------------------------------------------------------------------------
// Sense-reversing grid barrier. All NBLK blocks are resident (grid <= SMs).
// Writer path: publish memory (threadfence before arrive); last arrival resets
// count, fences, flips sense. Waiters spin on sense, then fence (acquire).
// ---------------------------------------------------------------------------
__device__ __forceinline__ void grid_barrier(int* lsense)
{
    __syncthreads();
    if (threadIdx.x == 0) {
        int ns = *lsense ^ 1;
        __threadfence();
        if (atomicAdd(&g_count, 1) == NBLK - 1) {
            g_count = 0;
            __threadfence();
            *(volatile int*)&g_sense = ns;
        } else {
            while (*(volatile int*)&g_sense != ns) { }
        }
        __threadfence();
        *lsense = ns;
    }
    __syncthreads();
}

// ---------------------------------------------------------------------------
// Kernel 2: persistent recurrence. 128 blocks x 256 threads, loops s=0..1023.
// Block owns 8 h-columns j0..j0+7 -> 32 gate columns:
//   gate col c (0..31) -> global gate index (c/8)*1024 + j0 + (c%8)
// Split-K: group g = tid/128 accumulates K half [g*512, g*512+512).
// Within group: 64x32 tile, 128 threads, 4x4 micro (tr=gt&15 rows 4tr..,
// tc=gt>>4 cols 4tc..). Partials summed across groups in Gs, then fused
// LSTM cell epilogue writes h,c into d_out ([2][NSTEP][B][H]).
// hprev/cprev stream via __ldcg (L2-only) so Uw slice stays L1-resident.
// ---------------------------------------------------------------------------
#define KC 32
#define NCHUNK 16   // 512 / KC per group

__global__ __launch_bounds__(256) void lstm_persistent(
    const float* __restrict__ Uw,  // [4H, H]
    float* __restrict__ out)       // [2, NSTEP, B, H]
{
    __shared__ float Hs[2][KC][68];   // [group][k][b], stride 68 (16B-aligned rows)
    __shared__ float Us[2][KC][36];   // [group][k][c]
    __shared__ float Gs[2][BB][33];   // per-group gate partials [b][c]

    const int tid = threadIdx.x;        // 256
    const int j0  = blockIdx.x * 8;     // 128 blocks
    const int g   = tid >> 7;           // k-half group 0/1
    const int gt  = tid & 127;
    const int tr  = gt & 15;            // rows 4*tr .. 4*tr+3
    const int tc  = gt >> 4;            // cols 4*tc .. 4*tc+3
    int lsense = 0;

    const size_t step_sz = (size_t)BB * HH;          // 65536
    const size_t c_base  = (size_t)NSTEP * step_sz;

    // Per-thread fill coordinates (constant across steps/chunks)
    int hb[4], hk[4];                   // Hs fill: 4 float4 per thread
#pragma unroll
    for (int l = 0; l < 4; l++) {
        int fq = l * 128 + gt;          // 0..511
        hb[l] = fq >> 3;                // b 0..63
        hk[l] = (fq & 7) * 4;           // kq 0..28
    }
    int uc[2], uk[2];
    size_t urow[2];                     // Us fill: 2 float4 per thread
#pragma unroll
    for (int l = 0; l < 2; l++) {
        int fq = l * 128 + gt;          // 0..255
        uc[l] = fq >> 3;                // c 0..31
        uk[l] = (fq & 7) * 4;
        int gc = (uc[l] >> 3) * HH + j0 + (uc[l] & 7);
        urow[l] = (size_t)gc * HH;
    }
    const int kbase0 = g * 512;

    for (int s = 0; s < NSTEP; s++) {
        const int t = s >> 1;
        float acc[4][4];
#pragma unroll
        for (int i = 0; i < 4; i++)
#pragma unroll
            for (int j = 0; j < 4; j++) acc[i][j] = 0.f;

        if (s > 0) {
            const float* hprev = out + (size_t)(s - 1) * step_sz;

            // Prefetch chunk 0 into registers
            float4 hreg[4], ureg[2];
#pragma unroll
            for (int l = 0; l < 4; l++)
                hreg[l] = __ldcg((const float4*)(hprev + (size_t)hb[l] * HH + kbase0 + hk[l]));
#pragma unroll
            for (int l = 0; l < 2; l++)
                ureg[l] = *(const float4*)(Uw + urow[l] + kbase0 + uk[l]);

            for (int chunk = 0; chunk < NCHUNK; chunk++) {
                // Commit prefetched tile to shared
#pragma unroll
                for (int l = 0; l < 4; l++) {
                    Hs[g][hk[l] + 0][hb[l]] = hreg[l].x;
                    Hs[g][hk[l] + 1][hb[l]] = hreg[l].y;
                    Hs[g][hk[l] + 2][hb[l]] = hreg[l].z;
                    Hs[g][hk[l] + 3][hb[l]] = hreg[l].w;
                }
#pragma unroll
                for (int l = 0; l < 2; l++) {
                    Us[g][uk[l] + 0][uc[l]] = ureg[l].x;
                    Us[g][uk[l] + 1][uc[l]] = ureg[l].y;
                    Us[g][uk[l] + 2][uc[l]] = ureg[l].z;
                    Us[g][uk[l] + 3][uc[l]] = ureg[l].w;
                }
                __syncthreads();

                // Prefetch next chunk while computing this one
                if (chunk + 1 < NCHUNK) {
                    int kb = kbase0 + (chunk + 1) * KC;
#pragma unroll
                    for (int l = 0; l < 4; l++)
                        hreg[l] = __ldcg((const float4*)(hprev + (size_t)hb[l] * HH + kb + hk[l]));
#pragma unroll
                    for (int l = 0; l < 2; l++)
                        ureg[l] = *(const float4*)(Uw + urow[l] + kb + uk[l]);
                }

#pragma unroll
                for (int kk = 0; kk < KC; kk++) {
                    const float4 a  = *(const float4*)&Hs[g][kk][4 * tr];
                    const float4 bv = *(const float4*)&Us[g][kk][4 * tc];
                    acc[0][0] += a.x * bv.x; acc[0][1] += a.x * bv.y;
                    acc[0][2] += a.x * bv.z; acc[0][3] += a.x * bv.w;
                    acc[1][0] += a.y * bv.x; acc[1][1] += a.y * bv.y;
                    acc[1][2] += a.y * bv.z; acc[1][3] += a.y * bv.w;
                    acc[2][0] += a.z * bv.x; acc[2][1] += a.z * bv.y;
                    acc[2][2] += a.z * bv.z; acc[2][3] += a.z * bv.w;
                    acc[3][0] += a.w * bv.x; acc[3][1] += a.w * bv.y;
                    acc[3][2] += a.w * bv.z; acc[3][3] += a.w * bv.w;
                }
                __syncthreads();
            }
        }

        // Stash group partials
#pragma unroll
        for (int i = 0; i < 4; i++)
#pragma unroll
            for (int j = 0; j < 4; j++)
                Gs[g][4 * tr + i][4 * tc + j] = acc[i][j];
        __syncthreads();

        // Fused LSTM cell epilogue: 512 cells, 2 per thread
        const float* xg    = g_xg + ((size_t)t * BB) * G4;
        const float* cprev = out + c_base + (size_t)(s > 0 ? s - 1 : 0) * step_sz;
#pragma unroll
        for (int l = 0; l < 2; l++) {
            int idx = l * 256 + tid;   // 0..511
            int b   = idx >> 3;
            int jj  = idx & 7;
            int j   = j0 + jj;
            const float* xrow = xg + (size_t)b * G4;

            float gi = Gs[0][b][jj]      + Gs[1][b][jj]      + xrow[j];
            float gf = Gs[0][b][8 + jj]  + Gs[1][b][8 + jj]  + xrow[HH + j];
            float gg = Gs[0][b][16 + jj] + Gs[1][b][16 + jj] + xrow[2 * HH + j];
            float go = Gs[0][b][24 + jj] + Gs[1][b][24 + jj] + xrow[3 * HH + j];

            float cp = (s > 0) ? __ldcg(cprev + (size_t)b * HH + j) : 0.f;

            float si = 1.f / (1.f + __expf(-gi));
            float sf = 1.f / (1.f + __expf(-gf));
            float so = 1.f / (1.f + __expf(-go));
            float tg = tanhf(gg);

            float cn = cp * sf + si * tg;
            float hn = so * tanhf(cn);

            out[(size_t)s * step_sz + (size_t)b * HH + j]          = hn;
            out[c_base + (size_t)s * step_sz + (size_t)b * HH + j] = cn;
        }

        // Publish h/c of step s to all blocks before step s+1 reads them.
        grid_barrier(&lsense);
    }
}

// ---------------------------------------------------------------------------
extern "C" void kernel_launch(void* const* d_in, const int* in_sizes, int n_in,
                              void* d_out, int out_size)
{
    const float* x  = (const float*)d_in[0];
    const float* Ww = (const float*)d_in[1];
    const float* bw = (const float*)d_in[2];
    const float* Uw = (const float*)d_in[3];
    const float* bu = (const float*)d_in[4];
    float* out = (float*)d_out;

    dim3 g1(G4 / XG_BN, (TT * BB) / XG_BM);  // (32, 256)
    xg_kernel<<<g1, 256>>>(x, Ww, bw, bu);

    lstm_persistent<<<NBLK, 256>>>(Uw, out);
}